// round 1
// baseline (speedup 1.0000x reference)
#include <cuda_runtime.h>
#include <cuda_bf16.h>

// RandomPrompter: out[b,c,h,w] = x[b,c,h,w] + (patch[c,h-r,w-c0] if inside 30x30 window else 0)
// Shapes: x [256,3,224,224] f32, patch [1,3,30,30] f32, offsets [256,2] i32.
//
// Memory-bound: 154 MB in + 154 MB out. One fused pass, float4-vectorized
// (W=224 % 4 == 0, so a float4 covers 4 contiguous w within one row).

#define BATCH 256
#define CH    3
#define HH    224
#define WW    224
#define PSZ   30

#define W4        (WW / 4)                        // 56 float4 per row
#define TOTAL_V4  (BATCH * CH * HH * W4)          // 9,633,792 float4s

__global__ __launch_bounds__(256) void random_prompter_kernel(
    const float4* __restrict__ x,
    const float* __restrict__ patch,
    const int2* __restrict__ offsets,
    float4* __restrict__ out)
{
    int v = blockIdx.x * blockDim.x + threadIdx.x;
    if (v >= TOTAL_V4) return;

    float4 val = x[v];

    // Decompose vec index: v = ((b*3 + ch)*224 + h)*56 + w4
    int w4 = v % W4;
    int t  = v / W4;
    int h  = t % HH;
    int t2 = t / HH;
    int c  = t2 % CH;
    int b  = t2 / CH;

    int2 off = offsets[b];           // (row, col), each in [0, 194)
    int dh = h - off.x;
    if ((unsigned)dh < (unsigned)PSZ) {
        const float* prow = patch + (c * PSZ + dh) * PSZ;
        int dw = w4 * 4 - off.y;     // patch-relative column of lane 0
        if ((unsigned)(dw + 0) < (unsigned)PSZ) val.x += prow[dw + 0];
        if ((unsigned)(dw + 1) < (unsigned)PSZ) val.y += prow[dw + 1];
        if ((unsigned)(dw + 2) < (unsigned)PSZ) val.z += prow[dw + 2];
        if ((unsigned)(dw + 3) < (unsigned)PSZ) val.w += prow[dw + 3];
    }

    out[v] = val;
}

extern "C" void kernel_launch(void* const* d_in, const int* in_sizes, int n_in,
                              void* d_out, int out_size)
{
    const float4* x      = (const float4*)d_in[0];
    const float*  patch  = (const float*)d_in[1];
    const int2*   offs   = (const int2*)d_in[2];
    float4*       out    = (float4*)d_out;

    const int threads = 256;
    const int blocks  = (TOTAL_V4 + threads - 1) / threads;  // 37632
    random_prompter_kernel<<<blocks, threads>>>(x, patch, offs, out);
}

// round 2
// speedup vs baseline: 1.0926x; 1.0926x over previous
#include <cuda_runtime.h>
#include <cuda_bf16.h>

// RandomPrompter: out[b,c,h,w] = x[b,c,h,w] + (patch inside per-sample 30x30 window)
// Shapes: x [256,3,224,224] f32, patch [1,3,30,30] f32, offsets [256,2] i32.
//
// Pure streaming (308 MB). Two float4s per thread (MLP=2), streaming cache
// hints (ldcs/stcs) since there is zero reuse.

#define BATCH 256
#define CH    3
#define HH    224
#define WW    224
#define PSZ   30

#define W4        (WW / 4)                        // 56 float4 per row
#define TOTAL_V4  (BATCH * CH * HH * W4)          // 9,633,792 float4s
#define VPT       2                               // float4s per thread
#define TPB       256
#define TILE      (TPB * VPT)                     // 512 float4s per block

__device__ __forceinline__ void patch_add(float4& val, int v,
                                          const float* __restrict__ patch,
                                          const int2* __restrict__ offsets)
{
    // v = ((b*3 + c)*224 + h)*56 + w4
    int w4 = v % W4;
    int t  = v / W4;
    int h  = t % HH;
    int t2 = t / HH;
    int c  = t2 % CH;
    int b  = t2 / CH;

    int2 off = __ldg(&offsets[b]);   // (row, col), each in [0, 194)
    int dh = h - off.x;
    if ((unsigned)dh < (unsigned)PSZ) {
        const float* prow = patch + (c * PSZ + dh) * PSZ;
        int dw = w4 * 4 - off.y;
        if ((unsigned)(dw + 0) < (unsigned)PSZ) val.x += __ldg(&prow[dw + 0]);
        if ((unsigned)(dw + 1) < (unsigned)PSZ) val.y += __ldg(&prow[dw + 1]);
        if ((unsigned)(dw + 2) < (unsigned)PSZ) val.z += __ldg(&prow[dw + 2]);
        if ((unsigned)(dw + 3) < (unsigned)PSZ) val.w += __ldg(&prow[dw + 3]);
    }
}

__global__ __launch_bounds__(TPB) void random_prompter_kernel(
    const float4* __restrict__ x,
    const float* __restrict__ patch,
    const int2* __restrict__ offsets,
    float4* __restrict__ out)
{
    int base = blockIdx.x * TILE + threadIdx.x;
    int v0 = base;
    int v1 = base + TPB;

    // TOTAL_V4 (9,633,792) is divisible by TILE (512): 18816 blocks, no tail.
    // Issue both loads before consuming either (MLP=2 per thread).
    float4 a = __ldcs(&x[v0]);
    float4 b = __ldcs(&x[v1]);

    patch_add(a, v0, patch, offsets);
    patch_add(b, v1, patch, offsets);

    __stcs(&out[v0], a);
    __stcs(&out[v1], b);
}

extern "C" void kernel_launch(void* const* d_in, const int* in_sizes, int n_in,
                              void* d_out, int out_size)
{
    const float4* x      = (const float4*)d_in[0];
    const float*  patch  = (const float*)d_in[1];
    const int2*   offs   = (const int2*)d_in[2];
    float4*       out    = (float4*)d_out;

    const int blocks = TOTAL_V4 / TILE;  // 18816, exact
    random_prompter_kernel<<<blocks, TPB>>>(x, patch, offs, out);
}